// round 10
// baseline (speedup 1.0000x reference)
#include <cuda_runtime.h>
#include <cstdint>
#include <cstddef>

#define NEXP 8
#define HDIM 1024
#define FDIM 4096

// intermediate activations [E, T, F] fp32 (static scratch; no allocs allowed)
__device__ float g_inter[(size_t)NEXP * 2048 * FDIM];

#define BM 128
#define BN 256
#define BK 16
#define A_BLK 576                       // bytes per (mt,ks) A fragment block
#define B_BLK 272                       // bytes per (nt,ks) B fragment block
#define A_REG_BYTES (16 * A_BLK)        // 8 mt * 2 ks = 9216
#define B_REG_BYTES (64 * B_BLK)        // 32 nt * 2 ks = 17408
#define STAGE (A_REG_BYTES + B_REG_BYTES)  // 26624
#define SMEM_DYN (2 * STAGE)            // 53248

__device__ __forceinline__ unsigned f2tf(float x) {
    unsigned u;
    asm("cvt.rna.tf32.f32 %0, %1;" : "=r"(u) : "f"(x));
    return u;
}

__device__ __forceinline__ void mma_tf32(float* c,
                                         unsigned a0, unsigned a1, unsigned a2, unsigned a3,
                                         unsigned b0, unsigned b1) {
    asm volatile(
        "mma.sync.aligned.m16n8k8.row.col.f32.tf32.tf32.f32 "
        "{%0,%1,%2,%3}, {%4,%5,%6,%7}, {%8,%9}, {%0,%1,%2,%3};"
        : "+f"(c[0]), "+f"(c[1]), "+f"(c[2]), "+f"(c[3])
        : "r"(a0), "r"(a1), "r"(a2), "r"(a3), "r"(b0), "r"(b1));
}

__device__ __forceinline__ float gelu_tanh(float x) {
    float x3 = x * x * x;
    return 0.5f * x * (1.0f + tanhf(0.7978845608028654f * (x + 0.044715f * x3)));
}

// C[M,N] = A[M,K] @ B[K,N] per expert (blockIdx.z), optional fused tanh-GELU.
// BM=128, BN=256, BK=16, 8 warps, warp tile 64x64.
// SMEM holds tf32 fragments in per-lane (fragment-major) order:
//   A: [mt(8)][ks(2)] blocks of 576B; lane offset = l*16 + (l>>3)*16; uint4 = (a0,a1,a2,a3)
//   B: [nt(32)][ks(2)] blocks of 272B; lane offset = l*8;             uint2 = (b0,b1)
template <bool GELU>
__global__ __launch_bounds__(256, 1)
void gemm_tc(const float* __restrict__ Aall, const float* __restrict__ Ball,
             float* __restrict__ Call, int M, int N, int K) {
    extern __shared__ __align__(16) char sm[];

    const int tid = threadIdx.x;
    const int lane = tid & 31;
    const int wid = tid >> 5;
    const int warp_m = wid & 1;    // 2 warps along M
    const int warp_n = wid >> 1;   // 4 warps along N
    const int e = blockIdx.z;
    const int mBase = blockIdx.x * BM;
    const int nBase = blockIdx.y * BN;

    const float* A = Aall + (size_t)e * M * K;
    const float* B = Ball + (size_t)e * K * N;
    float* C = Call + (size_t)e * M * N;

    // ---- A staging coords: thread handles row am, k-half ah (ks = ah) ----
    const int am = tid >> 1;            // 0..127
    const int ah = tid & 1;             // k 8*ah .. 8*ah+7
    const int ami = am & 15;
    const int amt = am >> 4;
    const float* aG = A + (size_t)(mBase + am) * K + 8 * ah;
    // store base (byte): block + 64*(mi&7) + 16*((mi&7)>>1) + 4*(mi>>3); +8*g per k-group, +16*j per value
    const int aSbase = (amt * 2 + ah) * A_BLK + (4 * (ami & 7)) * 16 +
                       ((ami & 7) >> 1) * 16 + (ami >> 3) * 4;

    // ---- B staging coords: thread handles k-row bk, 16-col group bnb ----
    const int bk = tid & 15;
    const int bnb = tid >> 4;           // 0..15, n group of 16
    const int br = bk & 3;
    const int breg = (bk >> 2) & 1;
    const int bks = bk >> 3;
    const float* bG = B + (size_t)bk * N + nBase + bnb * 16;
    const int bSbase = A_REG_BYTES + (bnb * 4 + bks) * B_BLK + 8 * br + 4 * breg;
    // addr(j,c) = bSbase + (j>>1)*544 + (j&1)*128 + 32*c

    float acc[4][8][4];
#pragma unroll
    for (int i = 0; i < 4; i++)
#pragma unroll
        for (int j = 0; j < 8; j++)
#pragma unroll
            for (int c = 0; c < 4; c++) acc[i][j][c] = 0.0f;

    const int ntile = K / BK;

    float4 ra[2], rb[4];

    // ---- prologue: load + stage tile 0 ----
#pragma unroll
    for (int g = 0; g < 2; ++g) ra[g] = *(const float4*)(aG + 4 * g);
#pragma unroll
    for (int j = 0; j < 4; ++j) rb[j] = *(const float4*)(bG + 4 * j);
    {
        char* stg = sm;
#pragma unroll
        for (int s = 0; s < 2; ++s) {           // h-swapped store order (bank-safe)
            const int g = s ^ ah;
            const float4 f = ra[g];
            char* p = stg + aSbase + 8 * g;
            *(unsigned*)(p +  0) = f2tf(f.x);
            *(unsigned*)(p + 16) = f2tf(f.y);
            *(unsigned*)(p + 32) = f2tf(f.z);
            *(unsigned*)(p + 48) = f2tf(f.w);
        }
#pragma unroll
        for (int j = 0; j < 4; ++j) {
            const float4 f = rb[j];
            char* p = stg + bSbase + (j >> 1) * 544 + (j & 1) * 128;
            *(unsigned*)(p +  0) = f2tf(f.x);
            *(unsigned*)(p + 32) = f2tf(f.y);
            *(unsigned*)(p + 64) = f2tf(f.z);
            *(unsigned*)(p + 96) = f2tf(f.w);
        }
    }
    __syncthreads();

    for (int t = 0; t < ntile; ++t) {
        // prefetch next tile globals
        if (t + 1 < ntile) {
#pragma unroll
            for (int g = 0; g < 2; ++g)
                ra[g] = *(const float4*)(aG + (size_t)(t + 1) * BK + 4 * g);
#pragma unroll
            for (int j = 0; j < 4; ++j)
                rb[j] = *(const float4*)(bG + (size_t)(t + 1) * BK * N + 4 * j);
        }

        // ---- compute on buffer t&1 ----
        const char* stg = sm + (t & 1) * STAGE;
#pragma unroll
        for (int ks = 0; ks < 2; ++ks) {
            uint4 af[4];
            uint2 bf[8];
#pragma unroll
            for (int i = 0; i < 4; ++i)
                af[i] = *(const uint4*)(stg + ((warp_m * 4 + i) * 2 + ks) * A_BLK +
                                        lane * 16 + (lane >> 3) * 16);
#pragma unroll
            for (int j = 0; j < 8; ++j)
                bf[j] = *(const uint2*)(stg + A_REG_BYTES +
                                        ((warp_n * 8 + j) * 2 + ks) * B_BLK + lane * 8);
#pragma unroll
            for (int i = 0; i < 4; ++i)
#pragma unroll
                for (int j = 0; j < 8; ++j)
                    mma_tf32(acc[i][j], af[i].x, af[i].y, af[i].z, af[i].w,
                             bf[j].x, bf[j].y);
        }

        // ---- stage next tile into other buffer ----
        if (t + 1 < ntile) {
            char* stw = sm + ((t + 1) & 1) * STAGE;
#pragma unroll
            for (int s = 0; s < 2; ++s) {
                const int g = s ^ ah;
                const float4 f = ra[g];
                char* p = stw + aSbase + 8 * g;
                *(unsigned*)(p +  0) = f2tf(f.x);
                *(unsigned*)(p + 16) = f2tf(f.y);
                *(unsigned*)(p + 32) = f2tf(f.z);
                *(unsigned*)(p + 48) = f2tf(f.w);
            }
#pragma unroll
            for (int j = 0; j < 4; ++j) {
                const float4 f = rb[j];
                char* p = stw + bSbase + (j >> 1) * 544 + (j & 1) * 128;
                *(unsigned*)(p +  0) = f2tf(f.x);
                *(unsigned*)(p + 32) = f2tf(f.y);
                *(unsigned*)(p + 64) = f2tf(f.z);
                *(unsigned*)(p + 96) = f2tf(f.w);
            }
            __syncthreads();
        }
    }

    // ---- epilogue: direct STG ----
    const int q = lane >> 2, r = lane & 3;
#pragma unroll
    for (int i = 0; i < 4; ++i) {
        const int row = mBase + warp_m * 64 + i * 16 + q;
#pragma unroll
        for (int j = 0; j < 8; ++j) {
            const int col = nBase + warp_n * 64 + j * 8 + 2 * r;
            float2 v0 = make_float2(acc[i][j][0], acc[i][j][1]);
            float2 v1 = make_float2(acc[i][j][2], acc[i][j][3]);
            if (GELU) {
                v0.x = gelu_tanh(v0.x); v0.y = gelu_tanh(v0.y);
                v1.x = gelu_tanh(v1.x); v1.y = gelu_tanh(v1.y);
            }
            *(float2*)(C + (size_t)row * N + col) = v0;
            *(float2*)(C + (size_t)(row + 8) * N + col) = v1;
        }
    }
}

extern "C" void kernel_launch(void* const* d_in, const int* in_sizes, int n_in,
                              void* d_out, int out_size) {
    const float* x  = (const float*)d_in[0];
    const float* w1 = (const float*)d_in[1];
    const float* w2 = (const float*)d_in[2];
    float* out = (float*)d_out;

    float* inter = nullptr;
    cudaGetSymbolAddress((void**)&inter, g_inter);

    const int T = (in_sizes[0] / HDIM) / NEXP;   // tokens per expert (2048)

    cudaFuncSetAttribute(gemm_tc<true>,  cudaFuncAttributeMaxDynamicSharedMemorySize, SMEM_DYN);
    cudaFuncSetAttribute(gemm_tc<false>, cudaFuncAttributeMaxDynamicSharedMemorySize, SMEM_DYN);

    // GEMM1 + GELU: [T,H] @ [H,F] -> inter [T,F] per expert
    dim3 g1(T / BM, FDIM / BN, NEXP);
    gemm_tc<true><<<g1, 256, SMEM_DYN>>>(x, w1, inter, T, FDIM, HDIM);
    // GEMM2: inter [T,F] @ [F,H] -> out [T,H] per expert
    dim3 g2(T / BM, HDIM / BN, NEXP);
    gemm_tc<false><<<g2, 256, SMEM_DYN>>>(inter, w2, out, T, HDIM, FDIM);
}

// round 12
// speedup vs baseline: 1.8727x; 1.8727x over previous
#include <cuda_runtime.h>
#include <cstdint>
#include <cstddef>

#define NEXP 8
#define HDIM 1024
#define FDIM 4096
#define TTOK 2048

// static device scratch (no allocs allowed)
__device__ float g_xtf [(size_t)NEXP * TTOK * HDIM];   // x pre-converted to tf32
__device__ float g_w1tf[(size_t)NEXP * HDIM * FDIM];   // w1 tf32
__device__ float g_w2tf[(size_t)NEXP * FDIM * HDIM];   // w2 tf32
__device__ float g_inter[(size_t)NEXP * TTOK * FDIM];  // gelu output (tf32-rounded)

#define BM 128
#define BN 128
#define BK 16
#define NSTAGE 4
#define AW_WORDS 2048                    // A stage: 128 rows x 16 words
#define BW_WORDS 2176                    // B stage: 16 rows x 136 words (pad)
#define A_REGION (NSTAGE * AW_WORDS)     // 8192 words
#define SMEM_WORDS (NSTAGE * (AW_WORDS + BW_WORDS))   // 16896
#define SMEM_DYN (SMEM_WORDS * 4)        // 67584 bytes

__device__ __forceinline__ unsigned f2tf(float x) {
    unsigned u;
    asm("cvt.rna.tf32.f32 %0, %1;" : "=r"(u) : "f"(x));
    return u;
}

__device__ __forceinline__ uint32_t smem_u32(const void* p) {
    uint32_t a;
    asm("{ .reg .u64 t; cvta.to.shared.u64 t, %1; cvt.u32.u64 %0, t; }" : "=r"(a) : "l"(p));
    return a;
}

__device__ __forceinline__ void cp16(uint32_t dst, const void* src) {
    asm volatile("cp.async.cg.shared.global [%0], [%1], 16;" :: "r"(dst), "l"(src));
}
__device__ __forceinline__ void cp_commit() {
    asm volatile("cp.async.commit_group;");
}
__device__ __forceinline__ void cp_wait2() {
    asm volatile("cp.async.wait_group %0;" :: "n"(NSTAGE - 2));
}

__device__ __forceinline__ void mma_tf32(float* c,
                                         unsigned a0, unsigned a1, unsigned a2, unsigned a3,
                                         unsigned b0, unsigned b1) {
    asm volatile(
        "mma.sync.aligned.m16n8k8.row.col.f32.tf32.tf32.f32 "
        "{%0,%1,%2,%3}, {%4,%5,%6,%7}, {%8,%9}, {%0,%1,%2,%3};"
        : "+f"(c[0]), "+f"(c[1]), "+f"(c[2]), "+f"(c[3])
        : "r"(a0), "r"(a1), "r"(a2), "r"(a3), "r"(b0), "r"(b1));
}

__device__ __forceinline__ float gelu_tanh(float x) {
    float x3 = x * x * x;
    return 0.5f * x * (1.0f + tanhf(0.7978845608028654f * (x + 0.044715f * x3)));
}

// elementwise fp32 -> tf32(rna)-rounded fp32, float4 grid-stride
__global__ void cvt_tf32_kernel(const float4* __restrict__ in, float4* __restrict__ out, int n4) {
    int i = blockIdx.x * blockDim.x + threadIdx.x;
    const int stride = gridDim.x * blockDim.x;
    for (; i < n4; i += stride) {
        float4 v = in[i];
        float4 o;
        o.x = __uint_as_float(f2tf(v.x));
        o.y = __uint_as_float(f2tf(v.y));
        o.z = __uint_as_float(f2tf(v.z));
        o.w = __uint_as_float(f2tf(v.w));
        out[i] = o;
    }
}

// C[M,N] = A[M,K] @ B[K,N] per expert (blockIdx.z). Inputs are tf32-rounded fp32.
// BM=BN=128, BK=16, 4 warps (2x2), warp tile 64x64, cp.async 4-stage pipeline.
// A smem: swizzled rows of 16 words: phys(m,k) = m*16 + (((k>>2) ^ ((m>>1)&3))<<2) + (k&3)
// B smem: row-major [k][n] padded LDB=136.
// GELU epilogue additionally rounds the output to tf32 (consumed raw by GEMM2).
template <bool GELU>
__global__ __launch_bounds__(128, 2)
void tc_gemm(const float* __restrict__ Aall, const float* __restrict__ Ball,
             float* __restrict__ Call, int M, int N, int K) {
    extern __shared__ unsigned sm[];
    const uint32_t sbase = smem_u32(sm);

    const int tid = threadIdx.x;
    const int lane = tid & 31;
    const int wid = tid >> 5;
    const int warp_m = wid & 1;
    const int warp_n = wid >> 1;
    const int e = blockIdx.z;
    const int mBase = blockIdx.x * BM;
    const int nBase = blockIdx.y * BN;

    const float* A = Aall + (size_t)e * M * K;
    const float* B = Ball + (size_t)e * K * N;
    float* C = Call + (size_t)e * M * N;

    // ---- staging coords: 4 x 16B granules each for A and B ----
    const int ar = tid >> 2;               // A row base (0..31), +32*i
    const int akq = tid & 3;               // A 16B granule within row
    const float* aG = A + (size_t)(mBase + ar) * K + akq * 4;
    const uint32_t aW0 = (uint32_t)ar * 16 + ((akq ^ ((ar >> 1) & 3)) << 2);  // +512*i

    const int bk = tid >> 5;               // B k-row base (0..3), +4*i
    const int bn4 = (tid & 31) * 4;        // B n offset
    const float* bG = B + (size_t)bk * N + nBase + bn4;
    const uint32_t bW0 = (uint32_t)bk * 136 + bn4;                            // +544*i

    const int ntile = K / BK;

    float acc[4][8][4];
#pragma unroll
    for (int i = 0; i < 4; i++)
#pragma unroll
        for (int j = 0; j < 8; j++)
#pragma unroll
            for (int c = 0; c < 4; c++) acc[i][j][c] = 0.0f;

    // issue stage s <- k-tile t (always commits, possibly empty)
    auto issue = [&](int s, int t) {
        if (t < ntile) {
            const uint32_t sa = sbase + (uint32_t)s * (AW_WORDS * 4);
            const float* ap = aG + (size_t)t * BK;
#pragma unroll
            for (int i = 0; i < 4; ++i)
                cp16(sa + (aW0 + i * 512) * 4, ap + (size_t)i * 32 * K);
            const uint32_t sb = sbase + (A_REGION + (uint32_t)s * BW_WORDS) * 4;
            const float* bp = bG + (size_t)t * BK * N;
#pragma unroll
            for (int i = 0; i < 4; ++i)
                cp16(sb + (bW0 + i * 544) * 4, bp + (size_t)i * 4 * N);
        }
        cp_commit();
    };

    // prologue: stages 0..NSTAGE-2
#pragma unroll
    for (int s = 0; s < NSTAGE - 1; ++s) issue(s, s);

    const int q = lane >> 2, r = lane & 3;
    const int sA = (q >> 1) & 3;

    for (int t = 0; t < ntile; ++t) {
        cp_wait2();
        __syncthreads();

        const unsigned* as = sm + (t % NSTAGE) * AW_WORDS;
        const unsigned* bs = sm + A_REGION + (t % NSTAGE) * BW_WORDS;
#pragma unroll
        for (int ks = 0; ks < 2; ++ks) {
            unsigned af[4][4];
#pragma unroll
            for (int mt = 0; mt < 4; ++mt) {
                const int m0 = warp_m * 64 + mt * 16 + q;
                const int base = m0 * 16 + r;
                const int cLo = ((2 * ks) ^ sA) << 2;
                const int cHi = ((2 * ks + 1) ^ sA) << 2;
                af[mt][0] = as[base + cLo];
                af[mt][1] = as[base + 128 + cLo];
                af[mt][2] = as[base + cHi];
                af[mt][3] = as[base + 128 + cHi];
            }
            unsigned bf[8][2];
#pragma unroll
            for (int nt = 0; nt < 8; ++nt) {
                const int n0 = warp_n * 64 + nt * 8 + q;
                bf[nt][0] = bs[(ks * 8 + r) * 136 + n0];
                bf[nt][1] = bs[(ks * 8 + 4 + r) * 136 + n0];
            }
#pragma unroll
            for (int mt = 0; mt < 4; ++mt)
#pragma unroll
                for (int nt = 0; nt < 8; ++nt)
                    mma_tf32(acc[mt][nt], af[mt][0], af[mt][1], af[mt][2], af[mt][3],
                             bf[nt][0], bf[nt][1]);
        }

        issue((t + NSTAGE - 1) % NSTAGE, t + NSTAGE - 1);
    }

    // ---- epilogue: direct STG (GELU path also rounds to tf32 for GEMM2) ----
#pragma unroll
    for (int mt = 0; mt < 4; ++mt) {
        const int row = mBase + warp_m * 64 + mt * 16 + q;
#pragma unroll
        for (int nt = 0; nt < 8; ++nt) {
            const int col = nBase + warp_n * 64 + nt * 8 + 2 * r;
            float2 v0 = make_float2(acc[mt][nt][0], acc[mt][nt][1]);
            float2 v1 = make_float2(acc[mt][nt][2], acc[mt][nt][3]);
            if (GELU) {
                v0.x = __uint_as_float(f2tf(gelu_tanh(v0.x)));
                v0.y = __uint_as_float(f2tf(gelu_tanh(v0.y)));
                v1.x = __uint_as_float(f2tf(gelu_tanh(v1.x)));
                v1.y = __uint_as_float(f2tf(gelu_tanh(v1.y)));
            }
            *(float2*)(C + (size_t)row * N + col) = v0;
            *(float2*)(C + (size_t)(row + 8) * N + col) = v1;
        }
    }
}

extern "C" void kernel_launch(void* const* d_in, const int* in_sizes, int n_in,
                              void* d_out, int out_size) {
    const float* x  = (const float*)d_in[0];
    const float* w1 = (const float*)d_in[1];
    const float* w2 = (const float*)d_in[2];
    float* out = (float*)d_out;

    float *xtf, *w1tf, *w2tf, *inter;
    cudaGetSymbolAddress((void**)&xtf,  g_xtf);
    cudaGetSymbolAddress((void**)&w1tf, g_w1tf);
    cudaGetSymbolAddress((void**)&w2tf, g_w2tf);
    cudaGetSymbolAddress((void**)&inter, g_inter);

    const int T = (in_sizes[0] / HDIM) / NEXP;   // tokens per expert (2048)

    // pre-convert inputs to tf32-rounded fp32
    cvt_tf32_kernel<<<2048, 256>>>((const float4*)x,  (float4*)xtf,  in_sizes[0] / 4);
    cvt_tf32_kernel<<<2048, 256>>>((const float4*)w1, (float4*)w1tf, in_sizes[1] / 4);
    cvt_tf32_kernel<<<2048, 256>>>((const float4*)w2, (float4*)w2tf, in_sizes[2] / 4);

    cudaFuncSetAttribute(tc_gemm<true>,  cudaFuncAttributeMaxDynamicSharedMemorySize, SMEM_DYN);
    cudaFuncSetAttribute(tc_gemm<false>, cudaFuncAttributeMaxDynamicSharedMemorySize, SMEM_DYN);

    // GEMM1 + GELU: [T,H] @ [H,F] -> inter [T,F] per expert
    dim3 g1(T / BM, FDIM / BN, NEXP);
    tc_gemm<true><<<g1, 128, SMEM_DYN>>>(xtf, w1tf, inter, T, FDIM, HDIM);
    // GEMM2: inter [T,F] @ [F,H] -> out [T,H] per expert
    dim3 g2(T / BM, HDIM / BN, NEXP);
    tc_gemm<false><<<g2, 128, SMEM_DYN>>>(inter, w2tf, out, T, HDIM, FDIM);
}

// round 13
// speedup vs baseline: 1.8871x; 1.0077x over previous
#include <cuda_runtime.h>
#include <cstdint>
#include <cstddef>

#define NEXP 8
#define HDIM 1024
#define FDIM 4096
#define TTOK 2048

// static device scratch (no allocs allowed)
__device__ float g_xtf [(size_t)NEXP * TTOK * HDIM];   // x pre-converted to tf32
__device__ float g_w1tf[(size_t)NEXP * HDIM * FDIM];   // w1 tf32
__device__ float g_w2tf[(size_t)NEXP * FDIM * HDIM];   // w2 tf32
__device__ float g_inter[(size_t)NEXP * TTOK * FDIM];  // gelu output (tf32-rounded)

#define BM 128
#define BN 128
#define BK 32
#define NSTAGE 3
#define A_WORDS 4096                     // 2 sub-tiles x (128 rows x 16 words)
#define B_WORDS 4352                     // 32 rows x 136 words (padded)
#define STAGE_WORDS (A_WORDS + B_WORDS)  // 8448
#define SMEM_DYN (NSTAGE * STAGE_WORDS * 4)   // 101376 bytes

__device__ __forceinline__ unsigned f2tf(float x) {
    unsigned u;
    asm("cvt.rna.tf32.f32 %0, %1;" : "=r"(u) : "f"(x));
    return u;
}

__device__ __forceinline__ uint32_t smem_u32(const void* p) {
    uint32_t a;
    asm("{ .reg .u64 t; cvta.to.shared.u64 t, %1; cvt.u32.u64 %0, t; }" : "=r"(a) : "l"(p));
    return a;
}

__device__ __forceinline__ void cp16(uint32_t dst, const void* src) {
    asm volatile("cp.async.cg.shared.global [%0], [%1], 16;" :: "r"(dst), "l"(src));
}
__device__ __forceinline__ void cp_commit() {
    asm volatile("cp.async.commit_group;");
}
__device__ __forceinline__ void cp_wait1() {
    asm volatile("cp.async.wait_group %0;" :: "n"(NSTAGE - 2));
}

__device__ __forceinline__ void mma_tf32(float* c,
                                         unsigned a0, unsigned a1, unsigned a2, unsigned a3,
                                         unsigned b0, unsigned b1) {
    asm volatile(
        "mma.sync.aligned.m16n8k8.row.col.f32.tf32.tf32.f32 "
        "{%0,%1,%2,%3}, {%4,%5,%6,%7}, {%8,%9}, {%0,%1,%2,%3};"
        : "+f"(c[0]), "+f"(c[1]), "+f"(c[2]), "+f"(c[3])
        : "r"(a0), "r"(a1), "r"(a2), "r"(a3), "r"(b0), "r"(b1));
}

__device__ __forceinline__ float gelu_tanh(float x) {
    float x3 = x * x * x;
    return 0.5f * x * (1.0f + tanhf(0.7978845608028654f * (x + 0.044715f * x3)));
}

// elementwise fp32 -> tf32(rna)-rounded fp32, float4 grid-stride
__global__ void cvt_tf32_kernel(const float4* __restrict__ in, float4* __restrict__ out, int n4) {
    int i = blockIdx.x * blockDim.x + threadIdx.x;
    const int stride = gridDim.x * blockDim.x;
    for (; i < n4; i += stride) {
        float4 v = in[i];
        float4 o;
        o.x = __uint_as_float(f2tf(v.x));
        o.y = __uint_as_float(f2tf(v.y));
        o.z = __uint_as_float(f2tf(v.z));
        o.w = __uint_as_float(f2tf(v.w));
        out[i] = o;
    }
}

// C[M,N] = A[M,K] @ B[K,N] per expert (blockIdx.z). Inputs are tf32-rounded fp32.
// BM=BN=128, BK=32, 4 warps (2x2), warp tile 64x64, cp.async 3-stage pipeline,
// per-ks fragment double-buffering (LDS for ks+1 overlaps MMAs of ks).
// A smem: per k-half sub-tile of 128x16 words, swizzled:
//   phys(m,k) = kh*2048 + m*16 + (((k>>2) ^ ((m>>1)&3))<<2) + (k&3)
// B smem: row-major [k][n], 32 rows, padded LDB=136.
template <bool GELU>
__global__ __launch_bounds__(128, 2)
void tc_gemm(const float* __restrict__ Aall, const float* __restrict__ Ball,
             float* __restrict__ Call, int M, int N, int K) {
    extern __shared__ unsigned sm[];
    const uint32_t sbase = smem_u32(sm);

    const int tid = threadIdx.x;
    const int lane = tid & 31;
    const int wid = tid >> 5;
    const int warp_m = wid & 1;
    const int warp_n = wid >> 1;
    const int e = blockIdx.z;
    const int mBase = blockIdx.x * BM;
    const int nBase = blockIdx.y * BN;

    const float* A = Aall + (size_t)e * M * K;
    const float* B = Ball + (size_t)e * K * N;
    float* C = Call + (size_t)e * M * N;

    // ---- staging coords ----
    const int ar = tid >> 2;               // A row base (0..31), rows ar+32*i
    const int akq = tid & 3;               // A 16B granule within 16-word row
    const float* aG = A + (size_t)(mBase + ar) * K + akq * 4;
    const uint32_t aW0 = (uint32_t)ar * 16 + ((akq ^ ((ar >> 1) & 3)) << 2);  // +512*i, +2048*kh

    const int bk = tid >> 5;               // B k-row base (0..3), rows bk+4*i
    const int bn4 = (tid & 31) * 4;        // B n offset
    const float* bG = B + (size_t)bk * N + nBase + bn4;
    const uint32_t bW0 = (uint32_t)bk * 136 + bn4;                            // +544*i

    const int ntile = K / BK;

    float acc[4][8][4];
#pragma unroll
    for (int i = 0; i < 4; i++)
#pragma unroll
        for (int j = 0; j < 8; j++)
#pragma unroll
            for (int c = 0; c < 4; c++) acc[i][j][c] = 0.0f;

    // issue stage s <- k-tile t (always commits, possibly empty)
    auto issue = [&](int s, int t) {
        if (t < ntile) {
            const uint32_t sa = sbase + (uint32_t)s * (STAGE_WORDS * 4);
            const float* ap = aG + (size_t)t * BK;
#pragma unroll
            for (int kh = 0; kh < 2; ++kh)
#pragma unroll
                for (int i = 0; i < 4; ++i)
                    cp16(sa + (kh * 2048u + aW0 + i * 512u) * 4,
                         ap + kh * 16 + (size_t)i * 32 * K);
            const uint32_t sb = sa + A_WORDS * 4;
            const float* bp = bG + (size_t)t * BK * N;
#pragma unroll
            for (int i = 0; i < 8; ++i)
                cp16(sb + (bW0 + i * 544u) * 4, bp + (size_t)i * 4 * N);
        }
        cp_commit();
    };

    // prologue: stages 0..NSTAGE-2
#pragma unroll
    for (int s = 0; s < NSTAGE - 1; ++s) issue(s, s);

    const int q = lane >> 2, r = lane & 3;
    const int sA = (q >> 1) & 3;

    unsigned af[2][4][4];
    unsigned bf[2][8][2];

    for (int t = 0; t < ntile; ++t) {
        cp_wait1();
        __syncthreads();

        const unsigned* as = sm + (t % NSTAGE) * STAGE_WORDS;
        const unsigned* bs = as + A_WORDS;

        // fragment loader for k-step ks (0..3) into buffer b
        auto ldfrag = [&](int ks, int b) {
            const unsigned* asub = as + (ks >> 1) * 2048;
            const int ksl = ks & 1;
            const int cLo = ((2 * ksl) ^ sA) << 2;
            const int cHi = ((2 * ksl + 1) ^ sA) << 2;
#pragma unroll
            for (int mt = 0; mt < 4; ++mt) {
                const int base = (warp_m * 64 + mt * 16 + q) * 16 + r;
                af[b][mt][0] = asub[base + cLo];
                af[b][mt][1] = asub[base + 128 + cLo];
                af[b][mt][2] = asub[base + cHi];
                af[b][mt][3] = asub[base + 128 + cHi];
            }
#pragma unroll
            for (int nt = 0; nt < 8; ++nt) {
                const int n0 = warp_n * 64 + nt * 8 + q;
                bf[b][nt][0] = bs[(ks * 8 + r) * 136 + n0];
                bf[b][nt][1] = bs[(ks * 8 + 4 + r) * 136 + n0];
            }
        };

        ldfrag(0, 0);
#pragma unroll
        for (int ks = 0; ks < 4; ++ks) {
            if (ks < 3) ldfrag(ks + 1, (ks + 1) & 1);
            const int b = ks & 1;
#pragma unroll
            for (int mt = 0; mt < 4; ++mt)
#pragma unroll
                for (int nt = 0; nt < 8; ++nt)
                    mma_tf32(acc[mt][nt],
                             af[b][mt][0], af[b][mt][1], af[b][mt][2], af[b][mt][3],
                             bf[b][nt][0], bf[b][nt][1]);
        }

        issue((t + NSTAGE - 1) % NSTAGE, t + NSTAGE - 1);
    }

    // ---- epilogue: direct STG (GELU path also rounds to tf32 for GEMM2) ----
#pragma unroll
    for (int mt = 0; mt < 4; ++mt) {
        const int row = mBase + warp_m * 64 + mt * 16 + q;
#pragma unroll
        for (int nt = 0; nt < 8; ++nt) {
            const int col = nBase + warp_n * 64 + nt * 8 + 2 * r;
            float2 v0 = make_float2(acc[mt][nt][0], acc[mt][nt][1]);
            float2 v1 = make_float2(acc[mt][nt][2], acc[mt][nt][3]);
            if (GELU) {
                v0.x = __uint_as_float(f2tf(gelu_tanh(v0.x)));
                v0.y = __uint_as_float(f2tf(gelu_tanh(v0.y)));
                v1.x = __uint_as_float(f2tf(gelu_tanh(v1.x)));
                v1.y = __uint_as_float(f2tf(gelu_tanh(v1.y)));
            }
            *(float2*)(C + (size_t)row * N + col) = v0;
            *(float2*)(C + (size_t)(row + 8) * N + col) = v1;
        }
    }
}

extern "C" void kernel_launch(void* const* d_in, const int* in_sizes, int n_in,
                              void* d_out, int out_size) {
    const float* x  = (const float*)d_in[0];
    const float* w1 = (const float*)d_in[1];
    const float* w2 = (const float*)d_in[2];
    float* out = (float*)d_out;

    float *xtf, *w1tf, *w2tf, *inter;
    cudaGetSymbolAddress((void**)&xtf,  g_xtf);
    cudaGetSymbolAddress((void**)&w1tf, g_w1tf);
    cudaGetSymbolAddress((void**)&w2tf, g_w2tf);
    cudaGetSymbolAddress((void**)&inter, g_inter);

    const int T = (in_sizes[0] / HDIM) / NEXP;   // tokens per expert (2048)

    // pre-convert inputs to tf32-rounded fp32
    cvt_tf32_kernel<<<2048, 256>>>((const float4*)x,  (float4*)xtf,  in_sizes[0] / 4);
    cvt_tf32_kernel<<<2048, 256>>>((const float4*)w1, (float4*)w1tf, in_sizes[1] / 4);
    cvt_tf32_kernel<<<2048, 256>>>((const float4*)w2, (float4*)w2tf, in_sizes[2] / 4);

    cudaFuncSetAttribute(tc_gemm<true>,  cudaFuncAttributeMaxDynamicSharedMemorySize, SMEM_DYN);
    cudaFuncSetAttribute(tc_gemm<false>, cudaFuncAttributeMaxDynamicSharedMemorySize, SMEM_DYN);

    // GEMM1 + GELU: [T,H] @ [H,F] -> inter [T,F] per expert
    dim3 g1(T / BM, FDIM / BN, NEXP);
    tc_gemm<true><<<g1, 128, SMEM_DYN>>>(xtf, w1tf, inter, T, FDIM, HDIM);
    // GEMM2: inter [T,F] @ [F,H] -> out [T,H] per expert
    dim3 g2(T / BM, HDIM / BN, NEXP);
    tc_gemm<false><<<g2, 128, SMEM_DYN>>>(inter, w2tf, out, T, HDIM, FDIM);
}